// round 1
// baseline (speedup 1.0000x reference)
#include <cuda_runtime.h>
#include <math.h>

// Problem constants
#define BATCH 4
#define TT    4096
#define DD    1024
#define LATD  1024
#define NH    8
#define DHD   128
#define TSPLIT 16
#define TCHUNK (TT / TSPLIT)   // 256

typedef long long ll;

// ---------------- scratch (device globals; no allocation allowed) ----------------
__device__ float g_Q[(size_t)BATCH * TT * LATD];            // 64 MB  [b*T+t][l]
__device__ float g_K[(size_t)BATCH * TT * LATD];            // 64 MB
__device__ float g_V[(size_t)BATCH * TT * DD];              // 64 MB
__device__ float g_Y[(size_t)BATCH * TT * DD];              // 64 MB
__device__ float g_Kvpart[(size_t)TSPLIT * 32 * 128 * 128]; // 33.5 MB [tc][z][i][j]
__device__ float g_Ksumpart[(size_t)TSPLIT * 32 * 128];     // [tc][z][i]
__device__ float g_Kvn[(size_t)32 * 128 * 128];             // [z][i][j]

// ---------------- generic tiled fp32 GEMM: C = A(MxK) * B(KxN) ----------------
// 128x128 block tile, BK=16, 256 threads, 8x8 accum per thread.
// Batched via blockIdx.z: per-z offsets = (z>>3)*hi + (z&7)*lo  (z = b*8+h).
// Requires M%128==0, N%128==0, K%16==0 (true for all uses here).
#define BM 128
#define BN 128
#define BK 16

__global__ __launch_bounds__(256) void sgemm_kernel(
    const float* __restrict__ A, const float* __restrict__ Bm, float* __restrict__ C,
    int K, int lda, int ldb, int ldc,
    ll aHi, ll aLo, ll bHi, ll bLo, ll cHi, ll cLo)
{
    const int z = blockIdx.z;
    A  += (ll)(z >> 3) * aHi + (ll)(z & 7) * aLo;
    Bm += (ll)(z >> 3) * bHi + (ll)(z & 7) * bLo;
    C  += (ll)(z >> 3) * cHi + (ll)(z & 7) * cLo;

    __shared__ float As[BK][BM];
    __shared__ float Bs[BK][BN];

    const int tid = threadIdx.x;
    const int ty = tid >> 4;       // 0..15 -> 8 rows each
    const int tx = tid & 15;       // 0..15 -> 8 cols each
    const int m0 = blockIdx.y * BM;
    const int n0 = blockIdx.x * BN;

    float acc[8][8];
#pragma unroll
    for (int i = 0; i < 8; i++)
#pragma unroll
        for (int j = 0; j < 8; j++) acc[i][j] = 0.f;

    for (int k0 = 0; k0 < K; k0 += BK) {
        // Load A tile: 128 rows x 16 cols -> As[k][m] (transposed into smem)
#pragma unroll
        for (int u = 0; u < 2; u++) {
            int idx = tid + u * 256;          // 0..511 float4s
            int r  = idx >> 2;                // 0..127
            int c4 = (idx & 3) << 2;          // 0,4,8,12
            float4 v = *(const float4*)&A[(ll)(m0 + r) * lda + k0 + c4];
            As[c4 + 0][r] = v.x; As[c4 + 1][r] = v.y;
            As[c4 + 2][r] = v.z; As[c4 + 3][r] = v.w;
        }
        // Load B tile: 16 rows x 128 cols
#pragma unroll
        for (int u = 0; u < 2; u++) {
            int idx = tid + u * 256;
            int r  = idx >> 5;                // 0..15
            int c4 = (idx & 31) << 2;         // 0..124
            *(float4*)&Bs[r][c4] = *(const float4*)&Bm[(ll)(k0 + r) * ldb + n0 + c4];
        }
        __syncthreads();

#pragma unroll
        for (int k = 0; k < BK; k++) {
            float4 a0 = *(const float4*)&As[k][ty * 8];
            float4 a1 = *(const float4*)&As[k][ty * 8 + 4];
            float4 b0 = *(const float4*)&Bs[k][tx * 8];
            float4 b1 = *(const float4*)&Bs[k][tx * 8 + 4];
            float a[8] = {a0.x,a0.y,a0.z,a0.w,a1.x,a1.y,a1.z,a1.w};
            float b[8] = {b0.x,b0.y,b0.z,b0.w,b1.x,b1.y,b1.z,b1.w};
#pragma unroll
            for (int i = 0; i < 8; i++)
#pragma unroll
                for (int j = 0; j < 8; j++) acc[i][j] += a[i] * b[j];
        }
        __syncthreads();
    }

#pragma unroll
    for (int i = 0; i < 8; i++) {
        int r = m0 + ty * 8 + i;
#pragma unroll
        for (int j = 0; j < 8; j += 4) {
            *(float4*)&C[(ll)r * ldc + n0 + tx * 8 + j] =
                make_float4(acc[i][j], acc[i][j+1], acc[i][j+2], acc[i][j+3]);
        }
    }
}

// ---------------- softmax over per-head latent dim (128) of Q, in place ----------------
// One warp per 128-wide row. Total rows = B*T*H = 131072.
__global__ __launch_bounds__(256) void softmax128_kernel(float* __restrict__ Q)
{
    ll row = ((ll)blockIdx.x << 3) + (threadIdx.x >> 5);
    int lane = threadIdx.x & 31;
    float* p = Q + (row << 7);
    float4 v = *(float4*)&p[lane << 2];
    float m = fmaxf(fmaxf(v.x, v.y), fmaxf(v.z, v.w));
#pragma unroll
    for (int o = 16; o > 0; o >>= 1) m = fmaxf(m, __shfl_xor_sync(0xffffffffu, m, o));
    float4 e;
    e.x = expf(v.x - m); e.y = expf(v.y - m);
    e.z = expf(v.z - m); e.w = expf(v.w - m);
    float s = e.x + e.y + e.z + e.w;
#pragma unroll
    for (int o = 16; o > 0; o >>= 1) s += __shfl_xor_sync(0xffffffffu, s, o);
    float inv = 1.f / s;
    e.x *= inv; e.y *= inv; e.z *= inv; e.w *= inv;
    *(float4*)&p[lane << 2] = e;
}

// ---------------- Kv partial: per (z=b*8+h, tc) compute over a 256-token chunk ----------------
// Kvpart[tc][z][i][j] = sum_t exp(K[b,t,h*128+i]) * V[b,t,h*128+j]
// Ksumpart[tc][z][i]  = sum_t exp(K[b,t,h*128+i])
// (max subtraction cancels in Kv/Ksum; K ~ N(0,1) so exp is fp32-safe)
__global__ __launch_bounds__(256) void kv_partial_kernel(void)
{
    const int z  = blockIdx.x;     // 0..31
    const int tc = blockIdx.y;     // 0..15
    const int b = z >> 3, h = z & 7;
    const float* Ab = g_K + (ll)b * TT * LATD + h * DHD;  // [t][i], row stride LATD
    const float* Bb = g_V + (ll)b * TT * DD   + h * DHD;  // [t][j], row stride DD

    __shared__ float As[16][128];
    __shared__ float Bs[16][128];

    const int tid = threadIdx.x;
    const int ty = tid >> 4, tx = tid & 15;
    float acc[8][8];
#pragma unroll
    for (int i = 0; i < 8; i++)
#pragma unroll
        for (int j = 0; j < 8; j++) acc[i][j] = 0.f;
    float ksum = 0.f;  // valid for tid < 128 (i = tid)

    const int t0 = tc * TCHUNK;
    for (int tt = 0; tt < TCHUNK; tt += 16) {
#pragma unroll
        for (int u = 0; u < 2; u++) {
            int idx = tid + u * 256;          // 0..511
            int k  = idx >> 5;                // t-row within tile, 0..15
            int i4 = (idx & 31) << 2;         // 0..124
            ll trow = (ll)(t0 + tt + k);
            float4 va = *(const float4*)&Ab[trow * LATD + i4];
            As[k][i4 + 0] = expf(va.x); As[k][i4 + 1] = expf(va.y);
            As[k][i4 + 2] = expf(va.z); As[k][i4 + 3] = expf(va.w);
            *(float4*)&Bs[k][i4] = *(const float4*)&Bb[trow * DD + i4];
        }
        __syncthreads();

        if (tid < 128) {
#pragma unroll
            for (int k = 0; k < 16; k++) ksum += As[k][tid];
        }
#pragma unroll
        for (int k = 0; k < 16; k++) {
            float4 a0 = *(const float4*)&As[k][ty * 8];
            float4 a1 = *(const float4*)&As[k][ty * 8 + 4];
            float4 b0 = *(const float4*)&Bs[k][tx * 8];
            float4 b1 = *(const float4*)&Bs[k][tx * 8 + 4];
            float a[8] = {a0.x,a0.y,a0.z,a0.w,a1.x,a1.y,a1.z,a1.w};
            float b[8] = {b0.x,b0.y,b0.z,b0.w,b1.x,b1.y,b1.z,b1.w};
#pragma unroll
            for (int i = 0; i < 8; i++)
#pragma unroll
                for (int j = 0; j < 8; j++) acc[i][j] += a[i] * b[j];
        }
        __syncthreads();
    }

    float* Cp = g_Kvpart + ((ll)tc * 32 + z) * (128 * 128);
#pragma unroll
    for (int i = 0; i < 8; i++) {
        int r = ty * 8 + i;
#pragma unroll
        for (int j = 0; j < 8; j += 4) {
            *(float4*)&Cp[r * 128 + tx * 8 + j] =
                make_float4(acc[i][j], acc[i][j+1], acc[i][j+2], acc[i][j+3]);
        }
    }
    if (tid < 128) g_Ksumpart[((ll)tc * 32 + z) * 128 + tid] = ksum;
}

// ---------------- reduce partials + normalize: Kvn[z][i][j] = sum_tc Kv / sum_tc Ksum ----------------
__global__ __launch_bounds__(128) void kv_reduce_norm_kernel(void)
{
    const int j  = threadIdx.x;      // 0..127
    const int zi = blockIdx.x;       // z*128+i, 0..4095
    const int z = zi >> 7, i = zi & 127;
    float kv = 0.f, s = 0.f;
#pragma unroll
    for (int tc = 0; tc < TSPLIT; tc++) {
        kv += g_Kvpart[((ll)tc * 32 + z) * 16384 + i * 128 + j];
        s  += g_Ksumpart[((ll)tc * 32 + z) * 128 + i];
    }
    g_Kvn[(ll)z * 16384 + i * 128 + j] = kv / s;
}

// ---------------- launch ----------------
extern "C" void kernel_launch(void* const* d_in, const int* in_sizes, int n_in,
                              void* d_out, int out_size)
{
    const float* query = (const float*)d_in[0];
    const float* key   = (const float*)d_in[1];
    const float* wq    = (const float*)d_in[2];
    const float* wk    = (const float*)d_in[3];
    const float* wv    = (const float*)d_in[4];
    const float* wproj = (const float*)d_in[5];
    float* out = (float*)d_out;

    float *Q, *K, *V, *Y, *Kvn;
    cudaGetSymbolAddress((void**)&Q,   g_Q);
    cudaGetSymbolAddress((void**)&K,   g_K);
    cudaGetSymbolAddress((void**)&V,   g_V);
    cudaGetSymbolAddress((void**)&Y,   g_Y);
    cudaGetSymbolAddress((void**)&Kvn, g_Kvn);

    dim3 blk(256);
    const int MBT = BATCH * TT;   // 16384

    // Projections: Q = query*wq, K = key*wk, V = key*wv   (each [16384,1024]x[1024,1024])
    dim3 gproj(LATD / BN, MBT / BM, 1);
    sgemm_kernel<<<gproj, blk>>>(query, wq, Q, DD, DD, LATD, LATD, 0,0,0,0,0,0);
    sgemm_kernel<<<gproj, blk>>>(key,   wk, K, DD, DD, LATD, LATD, 0,0,0,0,0,0);
    sgemm_kernel<<<gproj, blk>>>(key,   wv, V, DD, DD, DD,   DD,   0,0,0,0,0,0);

    // softmax over 128-wide head slices of Q (in place)
    softmax128_kernel<<<(MBT * NH) / 8, 256>>>(Q);

    // Kv partials over 16 t-chunks, then reduce+normalize
    kv_partial_kernel<<<dim3(32, TSPLIT, 1), blk>>>();
    kv_reduce_norm_kernel<<<dim3(32 * 128, 1, 1), dim3(128)>>>();

    // Readout: per (b,h): Y[t, h*128+j] = Qs_slice[4096x128] * Kvn[128x128]
    dim3 gread(1, TT / BM, 32);
    sgemm_kernel<<<gread, blk>>>(Q, Kvn, Y, DHD, LATD, DHD, DD,
                                 (ll)TT * LATD, DHD,          // A: per-b, per-h
                                 (ll)8 * 128 * 128, 128 * 128, // B: Kvn per z
                                 (ll)TT * DD, DHD);            // C: per-b, per-h

    // Output projection: out = Y * out_proj  ([16384,1024]x[1024,1024])
    sgemm_kernel<<<gproj, blk>>>(Y, wproj, out, DD, DD, DD, DD, 0,0,0,0,0,0);
}

// round 2
// speedup vs baseline: 1.0003x; 1.0003x over previous
#include <cuda_runtime.h>
#include <math.h>

// Problem constants
#define BATCH 4
#define TT    4096
#define DD    1024
#define LATD  1024
#define NH    8
#define DHD   128
#define TSPLIT 16
#define TCHUNK (TT / TSPLIT)   // 256

typedef long long ll;

// ---------------- scratch (device globals; no allocation allowed) ----------------
__device__ float g_Q[(size_t)BATCH * TT * LATD];            // 64 MB  [b*T+t][l]
__device__ float g_K[(size_t)BATCH * TT * LATD];            // 64 MB
__device__ float g_V[(size_t)BATCH * TT * DD];              // 64 MB
__device__ float g_Y[(size_t)BATCH * TT * DD];              // 64 MB
__device__ float g_Kvpart[(size_t)TSPLIT * 32 * 128 * 128]; // 33.5 MB [tc][z][i][j]
__device__ float g_Ksumpart[(size_t)TSPLIT * 32 * 128];     // [tc][z][i]
__device__ float g_Kvn[(size_t)32 * 128 * 128];             // [z][i][j]

// ---------------- generic tiled fp32 GEMM: C = A(MxK) * B(KxN) ----------------
// 128x128 block tile, BK=16, 256 threads, 8x8 accum per thread.
// Batched via blockIdx.z: per-z offsets = (z>>3)*hi + (z&7)*lo  (z = b*8+h).
// Requires M%128==0, N%128==0, K%16==0 (true for all uses here).
#define BM 128
#define BN 128
#define BK 16

__global__ __launch_bounds__(256) void sgemm_kernel(
    const float* __restrict__ A, const float* __restrict__ Bm, float* __restrict__ C,
    int K, int lda, int ldb, int ldc,
    ll aHi, ll aLo, ll bHi, ll bLo, ll cHi, ll cLo)
{
    const int z = blockIdx.z;
    A  += (ll)(z >> 3) * aHi + (ll)(z & 7) * aLo;
    Bm += (ll)(z >> 3) * bHi + (ll)(z & 7) * bLo;
    C  += (ll)(z >> 3) * cHi + (ll)(z & 7) * cLo;

    __shared__ float As[BK][BM];
    __shared__ float Bs[BK][BN];

    const int tid = threadIdx.x;
    const int ty = tid >> 4;       // 0..15 -> 8 rows each
    const int tx = tid & 15;       // 0..15 -> 8 cols each
    const int m0 = blockIdx.y * BM;
    const int n0 = blockIdx.x * BN;

    float acc[8][8];
#pragma unroll
    for (int i = 0; i < 8; i++)
#pragma unroll
        for (int j = 0; j < 8; j++) acc[i][j] = 0.f;

    for (int k0 = 0; k0 < K; k0 += BK) {
        // Load A tile: 128 rows x 16 cols -> As[k][m] (transposed into smem)
#pragma unroll
        for (int u = 0; u < 2; u++) {
            int idx = tid + u * 256;          // 0..511 float4s
            int r  = idx >> 2;                // 0..127
            int c4 = (idx & 3) << 2;          // 0,4,8,12
            float4 v = *(const float4*)&A[(ll)(m0 + r) * lda + k0 + c4];
            As[c4 + 0][r] = v.x; As[c4 + 1][r] = v.y;
            As[c4 + 2][r] = v.z; As[c4 + 3][r] = v.w;
        }
        // Load B tile: 16 rows x 128 cols
#pragma unroll
        for (int u = 0; u < 2; u++) {
            int idx = tid + u * 256;
            int r  = idx >> 5;                // 0..15
            int c4 = (idx & 31) << 2;         // 0..124
            *(float4*)&Bs[r][c4] = *(const float4*)&Bm[(ll)(k0 + r) * ldb + n0 + c4];
        }
        __syncthreads();

#pragma unroll
        for (int k = 0; k < BK; k++) {
            float4 a0 = *(const float4*)&As[k][ty * 8];
            float4 a1 = *(const float4*)&As[k][ty * 8 + 4];
            float4 b0 = *(const float4*)&Bs[k][tx * 8];
            float4 b1 = *(const float4*)&Bs[k][tx * 8 + 4];
            float a[8] = {a0.x,a0.y,a0.z,a0.w,a1.x,a1.y,a1.z,a1.w};
            float b[8] = {b0.x,b0.y,b0.z,b0.w,b1.x,b1.y,b1.z,b1.w};
#pragma unroll
            for (int i = 0; i < 8; i++)
#pragma unroll
                for (int j = 0; j < 8; j++) acc[i][j] += a[i] * b[j];
        }
        __syncthreads();
    }

#pragma unroll
    for (int i = 0; i < 8; i++) {
        int r = m0 + ty * 8 + i;
#pragma unroll
        for (int j = 0; j < 8; j += 4) {
            *(float4*)&C[(ll)r * ldc + n0 + tx * 8 + j] =
                make_float4(acc[i][j], acc[i][j+1], acc[i][j+2], acc[i][j+3]);
        }
    }
}

// ---------------- softmax over per-head latent dim (128) of Q, in place ----------------
// One warp per 128-wide row. Total rows = B*T*H = 131072.
__global__ __launch_bounds__(256) void softmax128_kernel(float* __restrict__ Q)
{
    ll row = ((ll)blockIdx.x << 3) + (threadIdx.x >> 5);
    int lane = threadIdx.x & 31;
    float* p = Q + (row << 7);
    float4 v = *(float4*)&p[lane << 2];
    float m = fmaxf(fmaxf(v.x, v.y), fmaxf(v.z, v.w));
#pragma unroll
    for (int o = 16; o > 0; o >>= 1) m = fmaxf(m, __shfl_xor_sync(0xffffffffu, m, o));
    float4 e;
    e.x = expf(v.x - m); e.y = expf(v.y - m);
    e.z = expf(v.z - m); e.w = expf(v.w - m);
    float s = e.x + e.y + e.z + e.w;
#pragma unroll
    for (int o = 16; o > 0; o >>= 1) s += __shfl_xor_sync(0xffffffffu, s, o);
    float inv = 1.f / s;
    e.x *= inv; e.y *= inv; e.z *= inv; e.w *= inv;
    *(float4*)&p[lane << 2] = e;
}

// ---------------- Kv partial: per (z=b*8+h, tc) compute over a 256-token chunk ----------------
// Kvpart[tc][z][i][j] = sum_t exp(K[b,t,h*128+i]) * V[b,t,h*128+j]
// Ksumpart[tc][z][i]  = sum_t exp(K[b,t,h*128+i])
// (max subtraction cancels in Kv/Ksum; K ~ N(0,1) so exp is fp32-safe)
__global__ __launch_bounds__(256) void kv_partial_kernel(void)
{
    const int z  = blockIdx.x;     // 0..31
    const int tc = blockIdx.y;     // 0..15
    const int b = z >> 3, h = z & 7;
    const float* Ab = g_K + (ll)b * TT * LATD + h * DHD;  // [t][i], row stride LATD
    const float* Bb = g_V + (ll)b * TT * DD   + h * DHD;  // [t][j], row stride DD

    __shared__ float As[16][128];
    __shared__ float Bs[16][128];

    const int tid = threadIdx.x;
    const int ty = tid >> 4, tx = tid & 15;
    float acc[8][8];
#pragma unroll
    for (int i = 0; i < 8; i++)
#pragma unroll
        for (int j = 0; j < 8; j++) acc[i][j] = 0.f;
    float ksum = 0.f;  // valid for tid < 128 (i = tid)

    const int t0 = tc * TCHUNK;
    for (int tt = 0; tt < TCHUNK; tt += 16) {
#pragma unroll
        for (int u = 0; u < 2; u++) {
            int idx = tid + u * 256;          // 0..511
            int k  = idx >> 5;                // t-row within tile, 0..15
            int i4 = (idx & 31) << 2;         // 0..124
            ll trow = (ll)(t0 + tt + k);
            float4 va = *(const float4*)&Ab[trow * LATD + i4];
            As[k][i4 + 0] = expf(va.x); As[k][i4 + 1] = expf(va.y);
            As[k][i4 + 2] = expf(va.z); As[k][i4 + 3] = expf(va.w);
            *(float4*)&Bs[k][i4] = *(const float4*)&Bb[trow * DD + i4];
        }
        __syncthreads();

        if (tid < 128) {
#pragma unroll
            for (int k = 0; k < 16; k++) ksum += As[k][tid];
        }
#pragma unroll
        for (int k = 0; k < 16; k++) {
            float4 a0 = *(const float4*)&As[k][ty * 8];
            float4 a1 = *(const float4*)&As[k][ty * 8 + 4];
            float4 b0 = *(const float4*)&Bs[k][tx * 8];
            float4 b1 = *(const float4*)&Bs[k][tx * 8 + 4];
            float a[8] = {a0.x,a0.y,a0.z,a0.w,a1.x,a1.y,a1.z,a1.w};
            float b[8] = {b0.x,b0.y,b0.z,b0.w,b1.x,b1.y,b1.z,b1.w};
#pragma unroll
            for (int i = 0; i < 8; i++)
#pragma unroll
                for (int j = 0; j < 8; j++) acc[i][j] += a[i] * b[j];
        }
        __syncthreads();
    }

    float* Cp = g_Kvpart + ((ll)tc * 32 + z) * (128 * 128);
#pragma unroll
    for (int i = 0; i < 8; i++) {
        int r = ty * 8 + i;
#pragma unroll
        for (int j = 0; j < 8; j += 4) {
            *(float4*)&Cp[r * 128 + tx * 8 + j] =
                make_float4(acc[i][j], acc[i][j+1], acc[i][j+2], acc[i][j+3]);
        }
    }
    if (tid < 128) g_Ksumpart[((ll)tc * 32 + z) * 128 + tid] = ksum;
}

// ---------------- reduce partials + normalize: Kvn[z][i][j] = sum_tc Kv / sum_tc Ksum ----------------
__global__ __launch_bounds__(128) void kv_reduce_norm_kernel(void)
{
    const int j  = threadIdx.x;      // 0..127
    const int zi = blockIdx.x;       // z*128+i, 0..4095
    const int z = zi >> 7, i = zi & 127;
    float kv = 0.f, s = 0.f;
#pragma unroll
    for (int tc = 0; tc < TSPLIT; tc++) {
        kv += g_Kvpart[((ll)tc * 32 + z) * 16384 + i * 128 + j];
        s  += g_Ksumpart[((ll)tc * 32 + z) * 128 + i];
    }
    g_Kvn[(ll)z * 16384 + i * 128 + j] = kv / s;
}

// ---------------- launch ----------------
extern "C" void kernel_launch(void* const* d_in, const int* in_sizes, int n_in,
                              void* d_out, int out_size)
{
    const float* query = (const float*)d_in[0];
    const float* key   = (const float*)d_in[1];
    const float* wq    = (const float*)d_in[2];
    const float* wk    = (const float*)d_in[3];
    const float* wv    = (const float*)d_in[4];
    const float* wproj = (const float*)d_in[5];
    float* out = (float*)d_out;

    float *Q, *K, *V, *Y, *Kvn;
    cudaGetSymbolAddress((void**)&Q,   g_Q);
    cudaGetSymbolAddress((void**)&K,   g_K);
    cudaGetSymbolAddress((void**)&V,   g_V);
    cudaGetSymbolAddress((void**)&Y,   g_Y);
    cudaGetSymbolAddress((void**)&Kvn, g_Kvn);

    dim3 blk(256);
    const int MBT = BATCH * TT;   // 16384

    // Projections: Q = query*wq, K = key*wk, V = key*wv   (each [16384,1024]x[1024,1024])
    dim3 gproj(LATD / BN, MBT / BM, 1);
    sgemm_kernel<<<gproj, blk>>>(query, wq, Q, DD, DD, LATD, LATD, 0,0,0,0,0,0);
    sgemm_kernel<<<gproj, blk>>>(key,   wk, K, DD, DD, LATD, LATD, 0,0,0,0,0,0);
    sgemm_kernel<<<gproj, blk>>>(key,   wv, V, DD, DD, DD,   DD,   0,0,0,0,0,0);

    // softmax over 128-wide head slices of Q (in place)
    softmax128_kernel<<<(MBT * NH) / 8, 256>>>(Q);

    // Kv partials over 16 t-chunks, then reduce+normalize
    kv_partial_kernel<<<dim3(32, TSPLIT, 1), blk>>>();
    kv_reduce_norm_kernel<<<dim3(32 * 128, 1, 1), dim3(128)>>>();

    // Readout: per (b,h): Y[t, h*128+j] = Qs_slice[4096x128] * Kvn[128x128]
    dim3 gread(1, TT / BM, 32);
    sgemm_kernel<<<gread, blk>>>(Q, Kvn, Y, DHD, LATD, DHD, DD,
                                 (ll)TT * LATD, DHD,          // A: per-b, per-h
                                 (ll)8 * 128 * 128, 128 * 128, // B: Kvn per z
                                 (ll)TT * DD, DHD);            // C: per-b, per-h

    // Output projection: out = Y * out_proj  ([16384,1024]x[1024,1024])
    sgemm_kernel<<<gproj, blk>>>(Y, wproj, out, DD, DD, DD, DD, 0,0,0,0,0,0);
}

// round 4
// speedup vs baseline: 1.9595x; 1.9588x over previous
#include <cuda_runtime.h>
#include <cuda_bf16.h>
#include <math.h>
#include <stdint.h>

// Problem constants
#define BATCH 4
#define TT    4096
#define DD    1024
#define LATD  1024
#define NH    8
#define DHD   128
#define TSPLIT 16
#define TCHUNK (TT / TSPLIT)   // 256

typedef long long ll;

// ---------------- scratch (device globals; no allocation allowed) ----------------
__device__ float g_Q[(size_t)BATCH * TT * LATD];
__device__ float g_K[(size_t)BATCH * TT * LATD];
__device__ float g_V[(size_t)BATCH * TT * DD];
__device__ float g_Y[(size_t)BATCH * TT * DD];
__device__ float g_Kvpart[(size_t)TSPLIT * 32 * 128 * 128];
__device__ float g_Ksumpart[(size_t)TSPLIT * 32 * 128];
__device__ float g_Kvn[(size_t)32 * 128 * 128];
// bf16 split buffers
__device__ __nv_bfloat16 g_Ahi[(size_t)BATCH * TT * DD];
__device__ __nv_bfloat16 g_Alo[(size_t)BATCH * TT * DD];
__device__ __nv_bfloat16 g_Bhi[(size_t)DD * DD];   // transposed weight [N][K]
__device__ __nv_bfloat16 g_Blo[(size_t)DD * DD];

// ============================ PTX helpers (base sm_100-safe) ============================
__device__ __forceinline__ uint32_t smem_u32(const void* p) {
    uint32_t a;
    asm("{ .reg .u64 t; cvta.to.shared.u64 t, %1; cvt.u32.u64 %0, t; }" : "=r"(a) : "l"(p));
    return a;
}
#define CP_ASYNC16(s, g) asm volatile("cp.async.cg.shared.global [%0], [%1], 16;" :: "r"(s), "l"(g))
#define CP_COMMIT() asm volatile("cp.async.commit_group;" ::: "memory")
#define CP_WAIT(n)  asm volatile("cp.async.wait_group %0;" :: "n"(n) : "memory")

#define LDSM_X4(r0, r1, r2, r3, a) \
    asm volatile("ldmatrix.sync.aligned.m8n8.x4.shared.b16 {%0,%1,%2,%3}, [%4];" \
                 : "=r"(r0), "=r"(r1), "=r"(r2), "=r"(r3) : "r"(a))

#define MMA_BF16(c, a, b) \
    asm volatile("mma.sync.aligned.m16n8k16.row.col.f32.bf16.bf16.f32 " \
                 "{%0,%1,%2,%3}, {%4,%5,%6,%7}, {%8,%9}, {%0,%1,%2,%3};" \
                 : "+f"((c)[0]), "+f"((c)[1]), "+f"((c)[2]), "+f"((c)[3]) \
                 : "r"((a)[0]), "r"((a)[1]), "r"((a)[2]), "r"((a)[3]), \
                   "r"((b)[0]), "r"((b)[1]))

// ============================ split-bf16 HMMA GEMM ============================
// C[M,1024] = A[M,1024] x Bt[1024,1024]^T  (Bt is N-major = "col" operand)
// A = Ah + Al, B = Bh + Bl; compute AhBh + AlBh + AhBl in fp32 accum.
// CTA tile 128x128, K-chunk 32, 8 warps (warp tile 64x32), 3-stage cp.async.
#define NKC 32                  // 1024 / 32
#define ROWB 80                 // padded row stride bytes (64B data + 16B pad)
#define SUBT (128 * ROWB)       // 10240 B per sub-tile
#define STAGEB (4 * SUBT)       // Ah, Al, Bh, Bl = 40960 B
#define NSTAGE 3
#define GEMM_SMEM (NSTAGE * STAGEB)

__global__ __launch_bounds__(256) void hmma_gemm_kernel(
    const __nv_bfloat16* __restrict__ Ah, const __nv_bfloat16* __restrict__ Al,
    const __nv_bfloat16* __restrict__ Bh, const __nv_bfloat16* __restrict__ Bl,
    float* __restrict__ C)
{
    extern __shared__ char dsm[];
    const uint32_t sbase = smem_u32(dsm);

    const int tid = threadIdx.x;
    const int wid = tid >> 5, lane = tid & 31;
    const int wm = wid & 1;         // 0..1 -> 64-row half
    const int wn = wid >> 1;        // 0..3 -> 32-col quarter
    const int m0 = blockIdx.y * 128;
    const int n0 = blockIdx.x * 128;

    const __nv_bfloat16* src[4] = { Ah + (ll)m0 * 1024, Al + (ll)m0 * 1024,
                                    Bh + (ll)n0 * 1024, Bl + (ll)n0 * 1024 };

    // ---- stage loader: 4 sub-tiles, each 128 rows x 64B (32 bf16), rows padded to 80B ----
    auto load_stage = [&](int s, int kc) {
        uint32_t st = sbase + s * STAGEB;
        const int k0 = kc * 32;
#pragma unroll
        for (int sub = 0; sub < 4; sub++) {
            const __nv_bfloat16* g = src[sub] + k0;
#pragma unroll
            for (int u = 0; u < 2; u++) {
                int c = tid + u * 256;          // 0..511 16B-chunks
                int r = c >> 2, ch = c & 3;
                CP_ASYNC16(st + sub * SUBT + r * ROWB + ch * 16,
                           g + (ll)r * 1024 + ch * 8);
            }
        }
    };

    float acc[4][4][4];
#pragma unroll
    for (int i = 0; i < 4; i++)
#pragma unroll
        for (int j = 0; j < 4; j++)
#pragma unroll
            for (int v = 0; v < 4; v++) acc[i][j][v] = 0.f;

    // ldmatrix per-lane offsets (byte offsets within a sub-tile)
    const int arow_l = lane & 15, aseg = lane >> 4;                        // A
    const int brow_l = (lane & 7) + ((lane >> 4) << 3), bseg = (lane >> 3) & 1;  // B

    load_stage(0, 0); CP_COMMIT();
    load_stage(1, 1); CP_COMMIT();

    for (int kc = 0; kc < NKC; kc++) {
        CP_WAIT(1);
        __syncthreads();
        if (kc + 2 < NKC) load_stage((kc + 2) % NSTAGE, kc + 2);
        CP_COMMIT();   // one group per iter (empty near tail keeps wait counts aligned)

        const uint32_t st = sbase + (kc % NSTAGE) * STAGEB;
        const uint32_t sAh = st, sAl = st + SUBT, sBh = st + 2 * SUBT, sBl = st + 3 * SUBT;

#pragma unroll
        for (int ks = 0; ks < 2; ks++) {
            uint32_t ah[4][4], al[4][4], bh[4][2], bl[4][2];
#pragma unroll
            for (int mi = 0; mi < 4; mi++) {
                uint32_t off = (uint32_t)((wm * 64 + mi * 16 + arow_l) * ROWB + ks * 32 + aseg * 16);
                LDSM_X4(ah[mi][0], ah[mi][1], ah[mi][2], ah[mi][3], sAh + off);
                LDSM_X4(al[mi][0], al[mi][1], al[mi][2], al[mi][3], sAl + off);
            }
#pragma unroll
            for (int np = 0; np < 2; np++) {
                uint32_t off = (uint32_t)((wn * 32 + np * 16 + brow_l) * ROWB + ks * 32 + bseg * 16);
                LDSM_X4(bh[np*2][0], bh[np*2][1], bh[np*2+1][0], bh[np*2+1][1], sBh + off);
                LDSM_X4(bl[np*2][0], bl[np*2][1], bl[np*2+1][0], bl[np*2+1][1], sBl + off);
            }
#pragma unroll
            for (int mi = 0; mi < 4; mi++)
#pragma unroll
                for (int nt = 0; nt < 4; nt++) {
                    MMA_BF16(acc[mi][nt], ah[mi], bh[nt]);
                    MMA_BF16(acc[mi][nt], al[mi], bh[nt]);
                    MMA_BF16(acc[mi][nt], ah[mi], bl[nt]);
                }
        }
        __syncthreads();
    }

    // epilogue
    const int g = lane >> 2, tig = lane & 3;
#pragma unroll
    for (int mi = 0; mi < 4; mi++) {
        int row = m0 + wm * 64 + mi * 16 + g;
#pragma unroll
        for (int nt = 0; nt < 4; nt++) {
            int col = n0 + wn * 32 + nt * 8 + tig * 2;
            *(float2*)&C[(ll)row * 1024 + col]       = make_float2(acc[mi][nt][0], acc[mi][nt][1]);
            *(float2*)&C[(ll)(row + 8) * 1024 + col] = make_float2(acc[mi][nt][2], acc[mi][nt][3]);
        }
    }
}

// ============================ converters ============================
__global__ __launch_bounds__(256) void convA_kernel(const float* __restrict__ x,
                                                    __nv_bfloat16* __restrict__ hi,
                                                    __nv_bfloat16* __restrict__ lo, int n4)
{
    int i = blockIdx.x * 256 + threadIdx.x;
    if (i >= n4) return;
    float4 v = *(const float4*)&x[(ll)i * 4];
    __nv_bfloat16 h0 = __float2bfloat16(v.x), h1 = __float2bfloat16(v.y);
    __nv_bfloat16 h2 = __float2bfloat16(v.z), h3 = __float2bfloat16(v.w);
    __nv_bfloat16 l0 = __float2bfloat16(v.x - __bfloat162float(h0));
    __nv_bfloat16 l1 = __float2bfloat16(v.y - __bfloat162float(h1));
    __nv_bfloat16 l2 = __float2bfloat16(v.z - __bfloat162float(h2));
    __nv_bfloat16 l3 = __float2bfloat16(v.w - __bfloat162float(h3));
    *(__nv_bfloat162*)&hi[(ll)i * 4]     = __nv_bfloat162(h0, h1);
    *(__nv_bfloat162*)&hi[(ll)i * 4 + 2] = __nv_bfloat162(h2, h3);
    *(__nv_bfloat162*)&lo[(ll)i * 4]     = __nv_bfloat162(l0, l1);
    *(__nv_bfloat162*)&lo[(ll)i * 4 + 2] = __nv_bfloat162(l2, l3);
}

// weight transpose + split: W[1024,1024] row-major -> WT[n][k] hi/lo bf16
__global__ __launch_bounds__(1024) void convWT_kernel(const float* __restrict__ W,
                                                      __nv_bfloat16* __restrict__ hi,
                                                      __nv_bfloat16* __restrict__ lo)
{
    __shared__ float ts[32][33];
    int tx = threadIdx.x & 31, ty = threadIdx.x >> 5;
    int k0 = blockIdx.y * 32, n0 = blockIdx.x * 32;
    ts[ty][tx] = W[(ll)(k0 + ty) * 1024 + n0 + tx];
    __syncthreads();
    float v = ts[tx][ty];   // = W[k0+tx][n0+ty]
    __nv_bfloat16 h = __float2bfloat16(v);
    __nv_bfloat16 l = __float2bfloat16(v - __bfloat162float(h));
    hi[(ll)(n0 + ty) * 1024 + k0 + tx] = h;
    lo[(ll)(n0 + ty) * 1024 + k0 + tx] = l;
}

// ---------------- softmax over per-head latent dim (128) of Q, in place ----------------
__global__ __launch_bounds__(256) void softmax128_kernel(float* __restrict__ Q)
{
    ll row = ((ll)blockIdx.x << 3) + (threadIdx.x >> 5);
    int lane = threadIdx.x & 31;
    float* p = Q + (row << 7);
    float4 v = *(float4*)&p[lane << 2];
    float m = fmaxf(fmaxf(v.x, v.y), fmaxf(v.z, v.w));
#pragma unroll
    for (int o = 16; o > 0; o >>= 1) m = fmaxf(m, __shfl_xor_sync(0xffffffffu, m, o));
    float4 e;
    e.x = expf(v.x - m); e.y = expf(v.y - m);
    e.z = expf(v.z - m); e.w = expf(v.w - m);
    float s = e.x + e.y + e.z + e.w;
#pragma unroll
    for (int o = 16; o > 0; o >>= 1) s += __shfl_xor_sync(0xffffffffu, s, o);
    float inv = 1.f / s;
    e.x *= inv; e.y *= inv; e.z *= inv; e.w *= inv;
    *(float4*)&p[lane << 2] = e;
}

// ---------------- fp32 tiled GEMM (readout) ----------------
#define BM 128
#define BN 128
#define BK 16
__global__ __launch_bounds__(256) void sgemm_kernel(
    const float* __restrict__ A, const float* __restrict__ Bm, float* __restrict__ C,
    int K, int lda, int ldb, int ldc,
    ll aHi, ll aLo, ll bHi, ll bLo, ll cHi, ll cLo)
{
    const int z = blockIdx.z;
    A  += (ll)(z >> 3) * aHi + (ll)(z & 7) * aLo;
    Bm += (ll)(z >> 3) * bHi + (ll)(z & 7) * bLo;
    C  += (ll)(z >> 3) * cHi + (ll)(z & 7) * cLo;

    __shared__ float As[BK][BM];
    __shared__ float Bs[BK][BN];
    const int tid = threadIdx.x;
    const int ty = tid >> 4, tx = tid & 15;
    const int m0 = blockIdx.y * BM, n0 = blockIdx.x * BN;

    float acc[8][8];
#pragma unroll
    for (int i = 0; i < 8; i++)
#pragma unroll
        for (int j = 0; j < 8; j++) acc[i][j] = 0.f;

    for (int k0 = 0; k0 < K; k0 += BK) {
#pragma unroll
        for (int u = 0; u < 2; u++) {
            int idx = tid + u * 256;
            int r = idx >> 2, c4 = (idx & 3) << 2;
            float4 v = *(const float4*)&A[(ll)(m0 + r) * lda + k0 + c4];
            As[c4 + 0][r] = v.x; As[c4 + 1][r] = v.y;
            As[c4 + 2][r] = v.z; As[c4 + 3][r] = v.w;
        }
#pragma unroll
        for (int u = 0; u < 2; u++) {
            int idx = tid + u * 256;
            int r = idx >> 5, c4 = (idx & 31) << 2;
            *(float4*)&Bs[r][c4] = *(const float4*)&Bm[(ll)(k0 + r) * ldb + n0 + c4];
        }
        __syncthreads();
#pragma unroll
        for (int k = 0; k < BK; k++) {
            float4 a0 = *(const float4*)&As[k][ty * 8];
            float4 a1 = *(const float4*)&As[k][ty * 8 + 4];
            float4 b0 = *(const float4*)&Bs[k][tx * 8];
            float4 b1 = *(const float4*)&Bs[k][tx * 8 + 4];
            float a[8] = {a0.x,a0.y,a0.z,a0.w,a1.x,a1.y,a1.z,a1.w};
            float b[8] = {b0.x,b0.y,b0.z,b0.w,b1.x,b1.y,b1.z,b1.w};
#pragma unroll
            for (int i = 0; i < 8; i++)
#pragma unroll
                for (int j = 0; j < 8; j++) acc[i][j] += a[i] * b[j];
        }
        __syncthreads();
    }
#pragma unroll
    for (int i = 0; i < 8; i++) {
        int r = m0 + ty * 8 + i;
#pragma unroll
        for (int j = 0; j < 8; j += 4) {
            *(float4*)&C[(ll)r * ldc + n0 + tx * 8 + j] =
                make_float4(acc[i][j], acc[i][j+1], acc[i][j+2], acc[i][j+3]);
        }
    }
}

// ---------------- Kv partial over 256-token chunks ----------------
__global__ __launch_bounds__(256) void kv_partial_kernel(void)
{
    const int z  = blockIdx.x;
    const int tc = blockIdx.y;
    const int b = z >> 3, h = z & 7;
    const float* Ab = g_K + (ll)b * TT * LATD + h * DHD;
    const float* Bb = g_V + (ll)b * TT * DD   + h * DHD;

    __shared__ float As[16][128];
    __shared__ float Bs[16][128];
    const int tid = threadIdx.x;
    const int ty = tid >> 4, tx = tid & 15;
    float acc[8][8];
#pragma unroll
    for (int i = 0; i < 8; i++)
#pragma unroll
        for (int j = 0; j < 8; j++) acc[i][j] = 0.f;
    float ksum = 0.f;

    const int t0 = tc * TCHUNK;
    for (int tt = 0; tt < TCHUNK; tt += 16) {
#pragma unroll
        for (int u = 0; u < 2; u++) {
            int idx = tid + u * 256;
            int k = idx >> 5, i4 = (idx & 31) << 2;
            ll trow = (ll)(t0 + tt + k);
            float4 va = *(const float4*)&Ab[trow * LATD + i4];
            As[k][i4 + 0] = expf(va.x); As[k][i4 + 1] = expf(va.y);
            As[k][i4 + 2] = expf(va.z); As[k][i4 + 3] = expf(va.w);
            *(float4*)&Bs[k][i4] = *(const float4*)&Bb[trow * DD + i4];
        }
        __syncthreads();
        if (tid < 128) {
#pragma unroll
            for (int k = 0; k < 16; k++) ksum += As[k][tid];
        }
#pragma unroll
        for (int k = 0; k < 16; k++) {
            float4 a0 = *(const float4*)&As[k][ty * 8];
            float4 a1 = *(const float4*)&As[k][ty * 8 + 4];
            float4 b0 = *(const float4*)&Bs[k][tx * 8];
            float4 b1 = *(const float4*)&Bs[k][tx * 8 + 4];
            float a[8] = {a0.x,a0.y,a0.z,a0.w,a1.x,a1.y,a1.z,a1.w};
            float b[8] = {b0.x,b0.y,b0.z,b0.w,b1.x,b1.y,b1.z,b1.w};
#pragma unroll
            for (int i = 0; i < 8; i++)
#pragma unroll
                for (int j = 0; j < 8; j++) acc[i][j] += a[i] * b[j];
        }
        __syncthreads();
    }

    float* Cp = g_Kvpart + ((ll)tc * 32 + z) * (128 * 128);
#pragma unroll
    for (int i = 0; i < 8; i++) {
        int r = ty * 8 + i;
#pragma unroll
        for (int j = 0; j < 8; j += 4) {
            *(float4*)&Cp[r * 128 + tx * 8 + j] =
                make_float4(acc[i][j], acc[i][j+1], acc[i][j+2], acc[i][j+3]);
        }
    }
    if (tid < 128) g_Ksumpart[((ll)tc * 32 + z) * 128 + tid] = ksum;
}

__global__ __launch_bounds__(128) void kv_reduce_norm_kernel(void)
{
    const int j  = threadIdx.x;
    const int zi = blockIdx.x;
    const int z = zi >> 7, i = zi & 127;
    float kv = 0.f, s = 0.f;
#pragma unroll
    for (int tc = 0; tc < TSPLIT; tc++) {
        kv += g_Kvpart[((ll)tc * 32 + z) * 16384 + i * 128 + j];
        s  += g_Ksumpart[((ll)tc * 32 + z) * 128 + i];
    }
    g_Kvn[(ll)z * 16384 + i * 128 + j] = kv / s;
}

// ---------------- launch ----------------
extern "C" void kernel_launch(void* const* d_in, const int* in_sizes, int n_in,
                              void* d_out, int out_size)
{
    const float* query = (const float*)d_in[0];
    const float* key   = (const float*)d_in[1];
    const float* wq    = (const float*)d_in[2];
    const float* wk    = (const float*)d_in[3];
    const float* wv    = (const float*)d_in[4];
    const float* wproj = (const float*)d_in[5];
    float* out = (float*)d_out;

    float *Q, *K, *V, *Y, *Kvn;
    __nv_bfloat16 *Ahi, *Alo, *Bhi, *Blo;
    cudaGetSymbolAddress((void**)&Q,   g_Q);
    cudaGetSymbolAddress((void**)&K,   g_K);
    cudaGetSymbolAddress((void**)&V,   g_V);
    cudaGetSymbolAddress((void**)&Y,   g_Y);
    cudaGetSymbolAddress((void**)&Kvn, g_Kvn);
    cudaGetSymbolAddress((void**)&Ahi, g_Ahi);
    cudaGetSymbolAddress((void**)&Alo, g_Alo);
    cudaGetSymbolAddress((void**)&Bhi, g_Bhi);
    cudaGetSymbolAddress((void**)&Blo, g_Blo);

    cudaFuncSetAttribute(hmma_gemm_kernel, cudaFuncAttributeMaxDynamicSharedMemorySize, GEMM_SMEM);

    const int MBT = BATCH * TT;                 // 16384
    const int actN4 = MBT * DD / 4;
    dim3 gconvA((actN4 + 255) / 256), bconvA(256);
    dim3 gconvW(32, 32), bconvW(1024);
    dim3 ggemm(8, 128), bgemm(256);

    // ---- Q = query * wq ----
    convWT_kernel<<<gconvW, bconvW>>>(wq, Bhi, Blo);
    convA_kernel<<<gconvA, bconvA>>>(query, Ahi, Alo, actN4);
    hmma_gemm_kernel<<<ggemm, bgemm, GEMM_SMEM>>>(Ahi, Alo, Bhi, Blo, Q);

    // ---- K = key * wk ; V = key * wv (key converted once) ----
    convA_kernel<<<gconvA, bconvA>>>(key, Ahi, Alo, actN4);
    convWT_kernel<<<gconvW, bconvW>>>(wk, Bhi, Blo);
    hmma_gemm_kernel<<<ggemm, bgemm, GEMM_SMEM>>>(Ahi, Alo, Bhi, Blo, K);
    convWT_kernel<<<gconvW, bconvW>>>(wv, Bhi, Blo);
    hmma_gemm_kernel<<<ggemm, bgemm, GEMM_SMEM>>>(Ahi, Alo, Bhi, Blo, V);

    // ---- softmax(Q) in place ----
    softmax128_kernel<<<(MBT * NH) / 8, 256>>>(Q);

    // ---- Kv aggregation + normalize ----
    kv_partial_kernel<<<dim3(32, TSPLIT, 1), 256>>>();
    kv_reduce_norm_kernel<<<dim3(32 * 128, 1, 1), 128>>>();

    // ---- readout: per (b,h) Y = Qs[4096x128] * Kvn[128x128] (fp32) ----
    dim3 gread(1, TT / BM, 32);
    sgemm_kernel<<<gread, 256>>>(Q, Kvn, Y, DHD, LATD, DHD, DD,
                                 (ll)TT * LATD, DHD,
                                 (ll)8 * 128 * 128, 128 * 128,
                                 (ll)TT * DD, DHD);

    // ---- out = Y * out_proj ----
    convA_kernel<<<gconvA, bconvA>>>(Y, Ahi, Alo, actN4);
    convWT_kernel<<<gconvW, bconvW>>>(wproj, Bhi, Blo);
    hmma_gemm_kernel<<<ggemm, bgemm, GEMM_SMEM>>>(Ahi, Alo, Bhi, Blo, out);
}

// round 5
// speedup vs baseline: 2.2999x; 1.1737x over previous
#include <cuda_runtime.h>
#include <cuda_bf16.h>
#include <math.h>
#include <stdint.h>

// Problem constants
#define BATCH 4
#define TT    4096
#define DD    1024
#define LATD  1024
#define NH    8
#define DHD   128
#define TSPLIT 16
#define TCHUNK (TT / TSPLIT)   // 256

typedef long long ll;

// ---------------- scratch (device globals; no allocation allowed) ----------------
__device__ float g_Q[(size_t)BATCH * TT * LATD];
__device__ float g_K[(size_t)BATCH * TT * LATD];
__device__ float g_V[(size_t)BATCH * TT * DD];
__device__ float g_Z[(size_t)BATCH * DD * DD];           // fused Kvn@Wout, per-batch 1024x1024
__device__ float g_Kvpart[(size_t)TSPLIT * 32 * 128 * 128];
__device__ float g_Ksumpart[(size_t)TSPLIT * 32 * 128];
__device__ float g_Kvn[(size_t)32 * 128 * 128];
// bf16 split buffers
__device__ __nv_bfloat16 g_Ahi[(size_t)BATCH * TT * DD];
__device__ __nv_bfloat16 g_Alo[(size_t)BATCH * TT * DD];
__device__ __nv_bfloat16 g_Bhi[(size_t)BATCH * DD * DD];  // transposed weights [N][K] (batched for Z)
__device__ __nv_bfloat16 g_Blo[(size_t)BATCH * DD * DD];

// ============================ PTX helpers (base sm_100-safe) ============================
__device__ __forceinline__ uint32_t smem_u32(const void* p) {
    uint32_t a;
    asm("{ .reg .u64 t; cvta.to.shared.u64 t, %1; cvt.u32.u64 %0, t; }" : "=r"(a) : "l"(p));
    return a;
}
#define CP_ASYNC16(s, g) asm volatile("cp.async.cg.shared.global [%0], [%1], 16;" :: "r"(s), "l"(g))
#define CP_COMMIT() asm volatile("cp.async.commit_group;" ::: "memory")
#define CP_WAIT(n)  asm volatile("cp.async.wait_group %0;" :: "n"(n) : "memory")

#define LDSM_X4(r0, r1, r2, r3, a) \
    asm volatile("ldmatrix.sync.aligned.m8n8.x4.shared.b16 {%0,%1,%2,%3}, [%4];" \
                 : "=r"(r0), "=r"(r1), "=r"(r2), "=r"(r3) : "r"(a))

#define MMA_BF16(c, a, b) \
    asm volatile("mma.sync.aligned.m16n8k16.row.col.f32.bf16.bf16.f32 " \
                 "{%0,%1,%2,%3}, {%4,%5,%6,%7}, {%8,%9}, {%0,%1,%2,%3};" \
                 : "+f"((c)[0]), "+f"((c)[1]), "+f"((c)[2]), "+f"((c)[3]) \
                 : "r"((a)[0]), "r"((a)[1]), "r"((a)[2]), "r"((a)[3]), \
                   "r"((b)[0]), "r"((b)[1]))

// ============================ split-bf16 HMMA GEMM ============================
// C[M,1024] = A[M,1024] x Bt[1024,1024]^T  (Bt N-major => "col" operand)
// 3-term: AhBh + AlBh + AhBl, fp32 accum.
// CTA tile 128x128, 4 warps (warp tile 64x64), K-chunk 64, 3-stage cp.async.
// Batched via blockIdx.z with element strides aZ (A), bZ (B), cZ (C).
#define NKC 16                  // 1024 / 64
#define ROWB 144                // padded row stride bytes (128B data + 16B pad)
#define SUBT (128 * ROWB)       // 18432 B per sub-tile
#define STAGEB (4 * SUBT)       // Ah, Al, Bh, Bl = 73728 B
#define NSTAGE 3
#define GEMM_SMEM (NSTAGE * STAGEB)   // 221184 B

__global__ __launch_bounds__(128) void hmma_gemm_kernel(
    const __nv_bfloat16* __restrict__ Ah, const __nv_bfloat16* __restrict__ Al,
    const __nv_bfloat16* __restrict__ Bh, const __nv_bfloat16* __restrict__ Bl,
    float* __restrict__ C, ll aZ, ll bZ, ll cZ)
{
    extern __shared__ char dsm[];
    const uint32_t sbase = smem_u32(dsm);

    const int tid = threadIdx.x;
    const int wid = tid >> 5, lane = tid & 31;
    const int wm = wid & 1;         // 0..1 -> 64-row half
    const int wn = wid >> 1;        // 0..1 -> 64-col half
    const int m0 = blockIdx.y * 128;
    const int n0 = blockIdx.x * 128;
    const int z  = blockIdx.z;

    const __nv_bfloat16* src[4] = { Ah + (ll)z * aZ + (ll)m0 * 1024,
                                    Al + (ll)z * aZ + (ll)m0 * 1024,
                                    Bh + (ll)z * bZ + (ll)n0 * 1024,
                                    Bl + (ll)z * bZ + (ll)n0 * 1024 };
    C += (ll)z * cZ;

    // ---- stage loader: 4 sub-tiles, 128 rows x 128B data (rows padded to 144B) ----
    auto load_stage = [&](int s, int kc) {
        uint32_t st = sbase + s * STAGEB;
        const int k0 = kc * 64;
#pragma unroll
        for (int sub = 0; sub < 4; sub++) {
            const __nv_bfloat16* g = src[sub] + k0;
#pragma unroll
            for (int u = 0; u < 8; u++) {
                int idx = tid + u * 128;        // 0..1023 16B-chunks
                int r = idx >> 3, ch = idx & 7;
                CP_ASYNC16(st + sub * SUBT + r * ROWB + ch * 16,
                           g + (ll)r * 1024 + ch * 8);
            }
        }
    };

    float acc[4][8][4];
#pragma unroll
    for (int i = 0; i < 4; i++)
#pragma unroll
        for (int j = 0; j < 8; j++)
#pragma unroll
            for (int v = 0; v < 4; v++) acc[i][j][v] = 0.f;

    // ldmatrix per-lane row/segment
    const int arow_l = lane & 15, aseg = lane >> 4;
    const int brow_l = (lane & 7) + ((lane >> 4) << 3), bseg = (lane >> 3) & 1;

    load_stage(0, 0); CP_COMMIT();
    load_stage(1, 1); CP_COMMIT();

    for (int kc = 0; kc < NKC; kc++) {
        CP_WAIT(1);
        __syncthreads();
        if (kc + 2 < NKC) load_stage((kc + 2) % NSTAGE, kc + 2);
        CP_COMMIT();

        const uint32_t st = sbase + (kc % NSTAGE) * STAGEB;
        const uint32_t sAh = st, sAl = st + SUBT, sBh = st + 2 * SUBT, sBl = st + 3 * SUBT;

#pragma unroll
        for (int ks = 0; ks < 4; ks++) {
            uint32_t ah[4][4], al[4][4], bh[8][2], bl[8][2];
#pragma unroll
            for (int mi = 0; mi < 4; mi++) {
                uint32_t off = (uint32_t)((wm * 64 + mi * 16 + arow_l) * ROWB + ks * 32 + aseg * 16);
                LDSM_X4(ah[mi][0], ah[mi][1], ah[mi][2], ah[mi][3], sAh + off);
                LDSM_X4(al[mi][0], al[mi][1], al[mi][2], al[mi][3], sAl + off);
            }
#pragma unroll
            for (int np = 0; np < 4; np++) {
                uint32_t off = (uint32_t)((wn * 64 + np * 16 + brow_l) * ROWB + ks * 32 + bseg * 16);
                LDSM_X4(bh[np*2][0], bh[np*2][1], bh[np*2+1][0], bh[np*2+1][1], sBh + off);
                LDSM_X4(bl[np*2][0], bl[np*2][1], bl[np*2+1][0], bl[np*2+1][1], sBl + off);
            }
#pragma unroll
            for (int mi = 0; mi < 4; mi++)
#pragma unroll
                for (int nt = 0; nt < 8; nt++) {
                    MMA_BF16(acc[mi][nt], ah[mi], bh[nt]);
                    MMA_BF16(acc[mi][nt], al[mi], bh[nt]);
                    MMA_BF16(acc[mi][nt], ah[mi], bl[nt]);
                }
        }
        __syncthreads();
    }

    // epilogue
    const int g = lane >> 2, tig = lane & 3;
#pragma unroll
    for (int mi = 0; mi < 4; mi++) {
        int row = m0 + wm * 64 + mi * 16 + g;
#pragma unroll
        for (int nt = 0; nt < 8; nt++) {
            int col = n0 + wn * 64 + nt * 8 + tig * 2;
            *(float2*)&C[(ll)row * 1024 + col]       = make_float2(acc[mi][nt][0], acc[mi][nt][1]);
            *(float2*)&C[(ll)(row + 8) * 1024 + col] = make_float2(acc[mi][nt][2], acc[mi][nt][3]);
        }
    }
}

// ============================ converters ============================
__global__ __launch_bounds__(256) void convA_kernel(const float* __restrict__ x,
                                                    __nv_bfloat16* __restrict__ hi,
                                                    __nv_bfloat16* __restrict__ lo, int n4)
{
    int i = blockIdx.x * 256 + threadIdx.x;
    if (i >= n4) return;
    float4 v = *(const float4*)&x[(ll)i * 4];
    __nv_bfloat16 h0 = __float2bfloat16(v.x), h1 = __float2bfloat16(v.y);
    __nv_bfloat16 h2 = __float2bfloat16(v.z), h3 = __float2bfloat16(v.w);
    __nv_bfloat16 l0 = __float2bfloat16(v.x - __bfloat162float(h0));
    __nv_bfloat16 l1 = __float2bfloat16(v.y - __bfloat162float(h1));
    __nv_bfloat16 l2 = __float2bfloat16(v.z - __bfloat162float(h2));
    __nv_bfloat16 l3 = __float2bfloat16(v.w - __bfloat162float(h3));
    *(__nv_bfloat162*)&hi[(ll)i * 4]     = __nv_bfloat162(h0, h1);
    *(__nv_bfloat162*)&hi[(ll)i * 4 + 2] = __nv_bfloat162(h2, h3);
    *(__nv_bfloat162*)&lo[(ll)i * 4]     = __nv_bfloat162(l0, l1);
    *(__nv_bfloat162*)&lo[(ll)i * 4 + 2] = __nv_bfloat162(l2, l3);
}

// weight transpose + split: W[1024,1024] row-major -> WT[n][k] hi/lo bf16
__global__ __launch_bounds__(1024) void convWT_kernel(const float* __restrict__ W,
                                                      __nv_bfloat16* __restrict__ hi,
                                                      __nv_bfloat16* __restrict__ lo)
{
    __shared__ float ts[32][33];
    int tx = threadIdx.x & 31, ty = threadIdx.x >> 5;
    int k0 = blockIdx.y * 32, n0 = blockIdx.x * 32;
    ts[ty][tx] = W[(ll)(k0 + ty) * 1024 + n0 + tx];
    __syncthreads();
    float v = ts[tx][ty];   // = W[k0+tx][n0+ty]
    __nv_bfloat16 h = __float2bfloat16(v);
    __nv_bfloat16 l = __float2bfloat16(v - __bfloat162float(h));
    hi[(ll)(n0 + ty) * 1024 + k0 + tx] = h;
    lo[(ll)(n0 + ty) * 1024 + k0 + tx] = l;
}

// ---------------- softmax over per-head latent dim (128) of Q, in place ----------------
__global__ __launch_bounds__(256) void softmax128_kernel(float* __restrict__ Q)
{
    ll row = ((ll)blockIdx.x << 3) + (threadIdx.x >> 5);
    int lane = threadIdx.x & 31;
    float* p = Q + (row << 7);
    float4 v = *(float4*)&p[lane << 2];
    float m = fmaxf(fmaxf(v.x, v.y), fmaxf(v.z, v.w));
#pragma unroll
    for (int o = 16; o > 0; o >>= 1) m = fmaxf(m, __shfl_xor_sync(0xffffffffu, m, o));
    float4 e;
    e.x = expf(v.x - m); e.y = expf(v.y - m);
    e.z = expf(v.z - m); e.w = expf(v.w - m);
    float s = e.x + e.y + e.z + e.w;
#pragma unroll
    for (int o = 16; o > 0; o >>= 1) s += __shfl_xor_sync(0xffffffffu, s, o);
    float inv = 1.f / s;
    e.x *= inv; e.y *= inv; e.z *= inv; e.w *= inv;
    *(float4*)&p[lane << 2] = e;
}

// ---------------- fp32 tiled GEMM (used for the small Z = Kvn @ Wout_h) ----------------
#define BM 128
#define BN 128
#define BK 16
__global__ __launch_bounds__(256) void sgemm_kernel(
    const float* __restrict__ A, const float* __restrict__ Bm, float* __restrict__ C,
    int K, int lda, int ldb, int ldc,
    ll aHi, ll aLo, ll bHi, ll bLo, ll cHi, ll cLo)
{
    const int z = blockIdx.z;
    A  += (ll)(z >> 3) * aHi + (ll)(z & 7) * aLo;
    Bm += (ll)(z >> 3) * bHi + (ll)(z & 7) * bLo;
    C  += (ll)(z >> 3) * cHi + (ll)(z & 7) * cLo;

    __shared__ float As[BK][BM];
    __shared__ float Bs[BK][BN];
    const int tid = threadIdx.x;
    const int ty = tid >> 4, tx = tid & 15;
    const int m0 = blockIdx.y * BM, n0 = blockIdx.x * BN;

    float acc[8][8];
#pragma unroll
    for (int i = 0; i < 8; i++)
#pragma unroll
        for (int j = 0; j < 8; j++) acc[i][j] = 0.f;

    for (int k0 = 0; k0 < K; k0 += BK) {
#pragma unroll
        for (int u = 0; u < 2; u++) {
            int idx = tid + u * 256;
            int r = idx >> 2, c4 = (idx & 3) << 2;
            float4 v = *(const float4*)&A[(ll)(m0 + r) * lda + k0 + c4];
            As[c4 + 0][r] = v.x; As[c4 + 1][r] = v.y;
            As[c4 + 2][r] = v.z; As[c4 + 3][r] = v.w;
        }
#pragma unroll
        for (int u = 0; u < 2; u++) {
            int idx = tid + u * 256;
            int r = idx >> 5, c4 = (idx & 31) << 2;
            *(float4*)&Bs[r][c4] = *(const float4*)&Bm[(ll)(k0 + r) * ldb + n0 + c4];
        }
        __syncthreads();
#pragma unroll
        for (int k = 0; k < BK; k++) {
            float4 a0 = *(const float4*)&As[k][ty * 8];
            float4 a1 = *(const float4*)&As[k][ty * 8 + 4];
            float4 b0 = *(const float4*)&Bs[k][tx * 8];
            float4 b1 = *(const float4*)&Bs[k][tx * 8 + 4];
            float a[8] = {a0.x,a0.y,a0.z,a0.w,a1.x,a1.y,a1.z,a1.w};
            float b[8] = {b0.x,b0.y,b0.z,b0.w,b1.x,b1.y,b1.z,b1.w};
#pragma unroll
            for (int i = 0; i < 8; i++)
#pragma unroll
                for (int j = 0; j < 8; j++) acc[i][j] += a[i] * b[j];
        }
        __syncthreads();
    }
#pragma unroll
    for (int i = 0; i < 8; i++) {
        int r = m0 + ty * 8 + i;
#pragma unroll
        for (int j = 0; j < 8; j += 4) {
            *(float4*)&C[(ll)r * ldc + n0 + tx * 8 + j] =
                make_float4(acc[i][j], acc[i][j+1], acc[i][j+2], acc[i][j+3]);
        }
    }
}

// ---------------- Kv partial over 256-token chunks ----------------
__global__ __launch_bounds__(256) void kv_partial_kernel(void)
{
    const int z  = blockIdx.x;
    const int tc = blockIdx.y;
    const int b = z >> 3, h = z & 7;
    const float* Ab = g_K + (ll)b * TT * LATD + h * DHD;
    const float* Bb = g_V + (ll)b * TT * DD   + h * DHD;

    __shared__ float As[16][128];
    __shared__ float Bs[16][128];
    const int tid = threadIdx.x;
    const int ty = tid >> 4, tx = tid & 15;
    float acc[8][8];
#pragma unroll
    for (int i = 0; i < 8; i++)
#pragma unroll
        for (int j = 0; j < 8; j++) acc[i][j] = 0.f;
    float ksum = 0.f;

    const int t0 = tc * TCHUNK;
    for (int tt = 0; tt < TCHUNK; tt += 16) {
#pragma unroll
        for (int u = 0; u < 2; u++) {
            int idx = tid + u * 256;
            int k = idx >> 5, i4 = (idx & 31) << 2;
            ll trow = (ll)(t0 + tt + k);
            float4 va = *(const float4*)&Ab[trow * LATD + i4];
            As[k][i4 + 0] = expf(va.x); As[k][i4 + 1] = expf(va.y);
            As[k][i4 + 2] = expf(va.z); As[k][i4 + 3] = expf(va.w);
            *(float4*)&Bs[k][i4] = *(const float4*)&Bb[trow * DD + i4];
        }
        __syncthreads();
        if (tid < 128) {
#pragma unroll
            for (int k = 0; k < 16; k++) ksum += As[k][tid];
        }
#pragma unroll
        for (int k = 0; k < 16; k++) {
            float4 a0 = *(const float4*)&As[k][ty * 8];
            float4 a1 = *(const float4*)&As[k][ty * 8 + 4];
            float4 b0 = *(const float4*)&Bs[k][tx * 8];
            float4 b1 = *(const float4*)&Bs[k][tx * 8 + 4];
            float a[8] = {a0.x,a0.y,a0.z,a0.w,a1.x,a1.y,a1.z,a1.w};
            float b[8] = {b0.x,b0.y,b0.z,b0.w,b1.x,b1.y,b1.z,b1.w};
#pragma unroll
            for (int i = 0; i < 8; i++)
#pragma unroll
                for (int j = 0; j < 8; j++) acc[i][j] += a[i] * b[j];
        }
        __syncthreads();
    }

    float* Cp = g_Kvpart + ((ll)tc * 32 + z) * (128 * 128);
#pragma unroll
    for (int i = 0; i < 8; i++) {
        int r = ty * 8 + i;
#pragma unroll
        for (int j = 0; j < 8; j += 4) {
            *(float4*)&Cp[r * 128 + tx * 8 + j] =
                make_float4(acc[i][j], acc[i][j+1], acc[i][j+2], acc[i][j+3]);
        }
    }
    if (tid < 128) g_Ksumpart[((ll)tc * 32 + z) * 128 + tid] = ksum;
}

__global__ __launch_bounds__(128) void kv_reduce_norm_kernel(void)
{
    const int j  = threadIdx.x;
    const int zi = blockIdx.x;
    const int z = zi >> 7, i = zi & 127;
    float kv = 0.f, s = 0.f;
#pragma unroll
    for (int tc = 0; tc < TSPLIT; tc++) {
        kv += g_Kvpart[((ll)tc * 32 + z) * 16384 + i * 128 + j];
        s  += g_Ksumpart[((ll)tc * 32 + z) * 128 + i];
    }
    g_Kvn[(ll)z * 16384 + i * 128 + j] = kv / s;
}

// ---------------- launch ----------------
extern "C" void kernel_launch(void* const* d_in, const int* in_sizes, int n_in,
                              void* d_out, int out_size)
{
    const float* query = (const float*)d_in[0];
    const float* key   = (const float*)d_in[1];
    const float* wq    = (const float*)d_in[2];
    const float* wk    = (const float*)d_in[3];
    const float* wv    = (const float*)d_in[4];
    const float* wproj = (const float*)d_in[5];
    float* out = (float*)d_out;

    float *Q, *K, *V, *Z, *Kvn;
    __nv_bfloat16 *Ahi, *Alo, *Bhi, *Blo;
    cudaGetSymbolAddress((void**)&Q,   g_Q);
    cudaGetSymbolAddress((void**)&K,   g_K);
    cudaGetSymbolAddress((void**)&V,   g_V);
    cudaGetSymbolAddress((void**)&Z,   g_Z);
    cudaGetSymbolAddress((void**)&Kvn, g_Kvn);
    cudaGetSymbolAddress((void**)&Ahi, g_Ahi);
    cudaGetSymbolAddress((void**)&Alo, g_Alo);
    cudaGetSymbolAddress((void**)&Bhi, g_Bhi);
    cudaGetSymbolAddress((void**)&Blo, g_Blo);

    cudaFuncSetAttribute(hmma_gemm_kernel, cudaFuncAttributeMaxDynamicSharedMemorySize, GEMM_SMEM);

    const int MBT = BATCH * TT;                 // 16384
    const int actN4 = MBT * DD / 4;
    dim3 gconvA((actN4 + 255) / 256), bconvA(256);
    dim3 gconvW(32, 32), bconvW(1024);
    dim3 ggemm(8, 128, 1), bgemm(128);

    // ---- Q = query * wq ----
    convWT_kernel<<<gconvW, bconvW>>>(wq, Bhi, Blo);
    convA_kernel<<<gconvA, bconvA>>>(query, Ahi, Alo, actN4);
    hmma_gemm_kernel<<<ggemm, bgemm, GEMM_SMEM>>>(Ahi, Alo, Bhi, Blo, Q, 0, 0, 0);

    // ---- K = key * wk ; V = key * wv (key converted once) ----
    convA_kernel<<<gconvA, bconvA>>>(key, Ahi, Alo, actN4);
    convWT_kernel<<<gconvW, bconvW>>>(wk, Bhi, Blo);
    hmma_gemm_kernel<<<ggemm, bgemm, GEMM_SMEM>>>(Ahi, Alo, Bhi, Blo, K, 0, 0, 0);
    convWT_kernel<<<gconvW, bconvW>>>(wv, Bhi, Blo);
    hmma_gemm_kernel<<<ggemm, bgemm, GEMM_SMEM>>>(Ahi, Alo, Bhi, Blo, V, 0, 0, 0);

    // ---- softmax(Q) in place ----
    softmax128_kernel<<<(MBT * NH) / 8, 256>>>(Q);

    // ---- Kv aggregation + normalize -> Kvn[z=b*8+h][l][d] ----
    kv_partial_kernel<<<dim3(32, TSPLIT, 1), 256>>>();
    kv_reduce_norm_kernel<<<dim3(32 * 128, 1, 1), 128>>>();

    // ---- Z[b, h*128+l, n] = sum_d Kvn[b,h,l,d] * Wout[h*128+d, n]  (tiny fp32 GEMM) ----
    // z = b*8+h: A = Kvn + z*16384 (lda=128), B = Wout + h*131072 (ldb=1024),
    //            C = Z + b*1048576 + h*131072 (ldc=1024)
    dim3 gz(8, 1, 32);
    sgemm_kernel<<<gz, 256>>>(Kvn, wproj, Z, 128, 128, 1024, 1024,
                              (ll)8 * 16384, 16384,
                              0, 131072,
                              1048576, 131072);

    // ---- out[b] = Qs[b] @ Z[b]  (batched big GEMM over b) ----
    convA_kernel<<<gconvA, bconvA>>>(Q, Ahi, Alo, actN4);
    for (int b = 0; b < BATCH; b++)
        convWT_kernel<<<gconvW, bconvW>>>(Z + (ll)b * 1048576,
                                          Bhi + (ll)b * 1048576, Blo + (ll)b * 1048576);
    dim3 gout(8, 32, 4);
    hmma_gemm_kernel<<<gout, bgemm, GEMM_SMEM>>>(Ahi, Alo, Bhi, Blo, out,
                                                 (ll)TT * DD, (ll)DD * DD, (ll)TT * DD);
}